// round 1
// baseline (speedup 1.0000x reference)
#include <cuda_runtime.h>

#define N 8192
#define ROWS_PER_BLOCK 8
#define THREADS 256

__global__ __launch_bounds__(THREADS) void rnn_step_kernel(
    const float* __restrict__ x,
    const float* __restrict__ y,
    const float* __restrict__ W,
    float* __restrict__ out)
{
    __shared__ float r[N];  // tanh(y), staged once per block (32 KB)

    const int tid = threadIdx.x;

    // Stage r = tanh(y) into shared, vectorized.
    const float4* y4 = reinterpret_cast<const float4*>(y);
    float4* r4 = reinterpret_cast<float4*>(r);
    #pragma unroll
    for (int i = tid; i < N / 4; i += THREADS) {
        float4 v = y4[i];
        float4 t;
        t.x = tanhf(v.x);
        t.y = tanhf(v.y);
        t.z = tanhf(v.z);
        t.w = tanhf(v.w);
        r4[i] = t;
    }
    __syncthreads();

    const int warp = tid >> 5;
    const int lane = tid & 31;
    const int row  = blockIdx.x * ROWS_PER_BLOCK + warp;

    const float4* Wrow = reinterpret_cast<const float4*>(W + (size_t)row * N);

    // 8192 floats / (32 lanes * 4) = 64 float4 iterations per lane.
    // 4 independent accumulators -> 4-deep unroll for memory-level parallelism.
    float a0 = 0.f, a1 = 0.f, a2 = 0.f, a3 = 0.f;
    #pragma unroll
    for (int i = 0; i < 64; i += 4) {
        float4 w0 = Wrow[(i + 0) * 32 + lane];
        float4 w1 = Wrow[(i + 1) * 32 + lane];
        float4 w2 = Wrow[(i + 2) * 32 + lane];
        float4 w3 = Wrow[(i + 3) * 32 + lane];
        float4 v0 = r4[(i + 0) * 32 + lane];
        float4 v1 = r4[(i + 1) * 32 + lane];
        float4 v2 = r4[(i + 2) * 32 + lane];
        float4 v3 = r4[(i + 3) * 32 + lane];
        a0 += w0.x * v0.x + w0.y * v0.y + w0.z * v0.z + w0.w * v0.w;
        a1 += w1.x * v1.x + w1.y * v1.y + w1.z * v1.z + w1.w * v1.w;
        a2 += w2.x * v2.x + w2.y * v2.y + w2.z * v2.z + w2.w * v2.w;
        a3 += w3.x * v3.x + w3.y * v3.y + w3.z * v3.z + w3.w * v3.w;
    }
    float acc = (a0 + a1) + (a2 + a3);

    // Warp reduction
    #pragma unroll
    for (int off = 16; off > 0; off >>= 1)
        acc += __shfl_xor_sync(0xFFFFFFFFu, acc, off);

    if (lane == 0) {
        const float DT  = 1e-3f;
        const float TAU = 1e-2f;
        float yi = y[row];
        float dy = (-yi + acc + x[row]) / TAU;
        out[row] = yi + DT * dy;
    }
}

extern "C" void kernel_launch(void* const* d_in, const int* in_sizes, int n_in,
                              void* d_out, int out_size)
{
    const float* x = (const float*)d_in[0];
    const float* y = (const float*)d_in[1];
    const float* W = (const float*)d_in[2];
    float* out = (float*)d_out;

    dim3 grid(N / ROWS_PER_BLOCK);  // 1024 blocks
    dim3 block(THREADS);
    rnn_step_kernel<<<grid, block>>>(x, y, W, out);
}